// round 7
// baseline (speedup 1.0000x reference)
#include <cuda_runtime.h>
#include <math.h>

#define NN 50000
#define NE 800000
#define HD 64
#define NLAYERS 4
#define EK 193          // 2H + 1 + H
#define SA_STRIDE 197   // odd -> conflict-free column reads
#define SM_STRIDE 65    // odd -> conflict-free column reads

// ---- edge kernel smem layout (floats), 128 edges / 1024 threads ----
#define EW1_OFF   0                    // 193*64 = 12352
#define EW2_OFF   12352                // 64*64  = 4096
#define EWC1_OFF  16448                // 64*64  = 4096
#define EWC2_OFF  20544                // 64
#define EB1_OFF   20608                // 64
#define EB2_OFF   20672                // 64
#define EBC1_OFF  20736                // 64
#define EROW_OFF  20800                // 128 (int)
#define ECOL_OFF  20928                // 128 (int)
#define ERAD_OFF  21056                // 128
#define EEM_OFF   21184                // 128
#define ECD_OFF   21312                // 128*3 = 384
#define EA_OFF    21696                // 128*197 = 25216  (overlaid by sM1/sM2/sS)
#define EDGE_SMEM_FLOATS (EA_OFF + 128 * SA_STRIDE)   // 46912 floats
#define EDGE_SMEM (EDGE_SMEM_FLOATS * 4)              // 187,648 B

#define NODE_SMEM (25216 * 4)

// persistent scratch (no runtime allocation allowed)
__device__ float g_h[NN * HD];
__device__ float g_e[NE * HD];
__device__ float g_x[NN * 3];
__device__ float g_dx[NN * 3];    // zero-initialized; restored to zero after use
__device__ float g_agg[NN * HD];  // zero-initialized; restored to zero after use

__device__ __forceinline__ float silu_f(float v) {
    return v / (1.0f + __expf(-v));
}

// ---------------------------------------------------------------- embeddings
__global__ void k_node_embed(const float* __restrict__ h,
                             const float* __restrict__ W,
                             const float* __restrict__ b) {
    __shared__ float sW[16 * 64];
    __shared__ float sb[64];
    int tid = threadIdx.x;
    for (int i = tid; i < 16 * 64; i += blockDim.x) sW[i] = W[i];
    if (tid < 64) sb[tid] = b[tid];
    __syncthreads();
    int gid = blockIdx.x * blockDim.x + tid;
    if (gid >= NN * HD) return;
    int n = gid >> 6, j = gid & 63;
    float acc = sb[j];
#pragma unroll
    for (int k = 0; k < 16; k++) acc += h[n * 16 + k] * sW[k * 64 + j];
    g_h[gid] = acc;
}

__global__ void k_edge_embed(const float* __restrict__ ea,
                             const float* __restrict__ W,
                             const float* __restrict__ b) {
    __shared__ float sW[8 * 64];
    __shared__ float sb[64];
    int tid = threadIdx.x;
    for (int i = tid; i < 8 * 64; i += blockDim.x) sW[i] = W[i];
    if (tid < 64) sb[tid] = b[tid];
    __syncthreads();
    int gid = blockIdx.x * blockDim.x + tid;
    if (gid >= NE * HD) return;
    int e = gid >> 6, j = gid & 63;
    float acc = sb[j];
#pragma unroll
    for (int k = 0; k < 8; k++) acc += ea[e * 8 + k] * sW[k * 64 + j];
    g_e[gid] = acc;
}

__global__ void k_xinit(const float* __restrict__ x) {
    int i = blockIdx.x * blockDim.x + threadIdx.x;
    if (i < NN * 3) g_x[i] = x[i];
}

// ---------------------------------------------------------------- edge layer
// 1024 threads = 128 edges x 8 output-slices. Thread (el,q) computes outputs
// [q*8, q*8+8) of edge el. A-reads: odd-stride conflict-free scalar LDS.
// W-reads: warp-uniform broadcast LDS.128 (all lanes share q).
__global__ void __launch_bounds__(1024, 1)
k_edge(const float* __restrict__ eW1, const float* __restrict__ eb1,
       const float* __restrict__ eW2, const float* __restrict__ eb2,
       const float* __restrict__ cW1, const float* __restrict__ cb1,
       const float* __restrict__ cW2,
       const int* __restrict__ edge_index,
       const float* __restrict__ edge_mask) {
    extern __shared__ float smem[];
    float* sW1  = smem + EW1_OFF;
    float* sW2  = smem + EW2_OFF;
    float* sWc1 = smem + EWC1_OFF;
    float* sWc2 = smem + EWC2_OFF;
    float* sb1  = smem + EB1_OFF;
    float* sb2  = smem + EB2_OFF;
    float* sbc1 = smem + EBC1_OFF;
    int*   sRow = (int*)(smem + EROW_OFF);
    int*   sCol = (int*)(smem + ECOL_OFF);
    float* sRad = smem + ERAD_OFF;
    float* sEM  = smem + EEM_OFF;
    float* sCD  = smem + ECD_OFF;
    float* sA   = smem + EA_OFF;             // 128 x 197
    float* sM1  = smem + EA_OFF;             // overlay: 128 x 65 (8320)
    float* sM2  = smem + EA_OFF + 8320;      // overlay: 128 x 65 (8320)
    float* sS   = smem + EA_OFF + 16640;     // overlay: 128 x 8

    int tid = threadIdx.x;
    for (int i = tid; i < EK * 64; i += 1024) sW1[i] = eW1[i];
    for (int i = tid; i < 64 * 64; i += 1024) { sW2[i] = eW2[i]; sWc1[i] = cW1[i]; }
    if (tid < 64) { sWc2[tid] = cW2[tid]; sb1[tid] = eb1[tid]; sb2[tid] = eb2[tid]; sbc1[tid] = cb1[tid]; }

    int ebase = blockIdx.x * 128;
    if (tid < 128) {
        int e = ebase + tid;
        int r = edge_index[e];
        int c = edge_index[NE + e];
        sRow[tid] = r; sCol[tid] = c;
        float dx = g_x[r * 3 + 0] - g_x[c * 3 + 0];
        float dy = g_x[r * 3 + 1] - g_x[c * 3 + 1];
        float dz = g_x[r * 3 + 2] - g_x[c * 3 + 2];
        float rad = dx * dx + dy * dy + dz * dz;
        sRad[tid] = rad;
        float inv = 1.0f / (sqrtf(rad) + 1.0f);
        sCD[tid * 3 + 0] = dx * inv;
        sCD[tid * 3 + 1] = dy * inv;
        sCD[tid * 3 + 2] = dz * inv;
        sEM[tid] = edge_mask[e];
    }
    __syncthreads();

    // build A = [h[row] | h[col] | radial | e]  (128 x 193, stride 197)
    for (int i = tid; i < 128 * EK; i += 1024) {
        int el = i / EK;
        int k  = i - el * EK;
        float v;
        if (k < 64)        v = g_h[sRow[el] * 64 + k];
        else if (k < 128)  v = g_h[sCol[el] * 64 + (k - 64)];
        else if (k == 128) v = sRad[el];
        else               v = g_e[(size_t)(ebase + el) * 64 + (k - 129)];
        sA[el * SA_STRIDE + k] = v;
    }
    __syncthreads();

    int q  = tid >> 7;          // 0..7  (warp-uniform)
    int el = tid & 127;         // 0..127 (consecutive within warp)
    int c0 = q * 8;

    float acc[8];
#pragma unroll
    for (int j = 0; j < 8; j++) acc[j] = 0.0f;

    // GEMM1: out[el][c0..c0+8) over K=193
    {
        const float* ap = sA + el * SA_STRIDE;
        const float* wp = sW1 + c0;
#pragma unroll 4
        for (int k = 0; k < EK; k++) {
            float a = ap[k];
            float4 w0 = *(const float4*)(wp + k * 64);
            float4 w1 = *(const float4*)(wp + k * 64 + 4);
            acc[0] = fmaf(a, w0.x, acc[0]); acc[1] = fmaf(a, w0.y, acc[1]);
            acc[2] = fmaf(a, w0.z, acc[2]); acc[3] = fmaf(a, w0.w, acc[3]);
            acc[4] = fmaf(a, w1.x, acc[4]); acc[5] = fmaf(a, w1.y, acc[5]);
            acc[6] = fmaf(a, w1.z, acc[6]); acc[7] = fmaf(a, w1.w, acc[7]);
        }
    }
    __syncthreads();   // all sA reads complete; overlay region becomes free

    // m1 = silu(acc + b1) -> sM1 (stride 65, scalar conflict-free stores)
#pragma unroll
    for (int j = 0; j < 8; j++)
        sM1[el * SM_STRIDE + c0 + j] = silu_f(acc[j] + sb1[c0 + j]);
    __syncthreads();

    // GEMM2: K = 64, reads sM1
#pragma unroll
    for (int j = 0; j < 8; j++) acc[j] = 0.0f;
    {
        const float* ap = sM1 + el * SM_STRIDE;
        const float* wp = sW2 + c0;
#pragma unroll 4
        for (int k = 0; k < 64; k++) {
            float a = ap[k];
            float4 w0 = *(const float4*)(wp + k * 64);
            float4 w1 = *(const float4*)(wp + k * 64 + 4);
            acc[0] = fmaf(a, w0.x, acc[0]); acc[1] = fmaf(a, w0.y, acc[1]);
            acc[2] = fmaf(a, w0.z, acc[2]); acc[3] = fmaf(a, w0.w, acc[3]);
            acc[4] = fmaf(a, w1.x, acc[4]); acc[5] = fmaf(a, w1.y, acc[5]);
            acc[6] = fmaf(a, w1.z, acc[6]); acc[7] = fmaf(a, w1.w, acc[7]);
        }
    }

    // m = silu(acc + b2) * edge_mask -> g_e, g_agg (atomic), sM2
    {
        float em = sEM[el];
        float m[8];
#pragma unroll
        for (int j = 0; j < 8; j++) m[j] = silu_f(acc[j] + sb2[c0 + j]) * em;

        float* ge = g_e + (size_t)(ebase + el) * 64 + c0;
        *(float4*)(ge)     = make_float4(m[0], m[1], m[2], m[3]);
        *(float4*)(ge + 4) = make_float4(m[4], m[5], m[6], m[7]);

        int rw = sRow[el];
        float* ga = g_agg + (size_t)rw * 64 + c0;
#pragma unroll
        for (int j = 0; j < 8; j++) {
            sM2[el * SM_STRIDE + c0 + j] = m[j];
            atomicAdd(ga + j, m[j]);
        }
    }
    __syncthreads();

    // GEMM3 (coord head): c1 = silu(m@cW1+cb1); partial = sum_j c1[j]*cW2[j]
#pragma unroll
    for (int j = 0; j < 8; j++) acc[j] = 0.0f;
    {
        const float* ap = sM2 + el * SM_STRIDE;
        const float* wp = sWc1 + c0;
#pragma unroll 4
        for (int k = 0; k < 64; k++) {
            float a = ap[k];
            float4 w0 = *(const float4*)(wp + k * 64);
            float4 w1 = *(const float4*)(wp + k * 64 + 4);
            acc[0] = fmaf(a, w0.x, acc[0]); acc[1] = fmaf(a, w0.y, acc[1]);
            acc[2] = fmaf(a, w0.z, acc[2]); acc[3] = fmaf(a, w0.w, acc[3]);
            acc[4] = fmaf(a, w1.x, acc[4]); acc[5] = fmaf(a, w1.y, acc[5]);
            acc[6] = fmaf(a, w1.z, acc[6]); acc[7] = fmaf(a, w1.w, acc[7]);
        }
    }
    {
        float p = 0.0f;
#pragma unroll
        for (int j = 0; j < 8; j++)
            p += silu_f(acc[j] + sbc1[c0 + j]) * sWc2[c0 + j];
        sS[el * 8 + q] = p;
    }
    __syncthreads();
    if (tid < 128) {
        float s = 0.0f;
#pragma unroll
        for (int u = 0; u < 8; u++) s += sS[tid * 8 + u];
        int r = sRow[tid];
        atomicAdd(&g_dx[r * 3 + 0], sCD[tid * 3 + 0] * s);
        atomicAdd(&g_dx[r * 3 + 1], sCD[tid * 3 + 1] * s);
        atomicAdd(&g_dx[r * 3 + 2], sCD[tid * 3 + 2] * s);
    }
}

// ---------------------------------------------------------------- node layer
// Also performs the x update for its 64 nodes (edge scatters complete at
// kernel boundary): x = (x + dx) * mask; dx = 0.
__global__ void __launch_bounds__(256, 1)
k_node(const float* __restrict__ nW1, const float* __restrict__ nb1,
       const float* __restrict__ nW2, const float* __restrict__ nb2,
       const float* __restrict__ node_mask) {
    extern __shared__ float smem[];
    float* sW1 = smem;           // 128*64
    float* sW2 = smem + 8192;    // 64*64
    float* sb1 = smem + 12288;
    float* sb2 = smem + 12352;
    float* sA  = smem + 12416;   // 64 x 132
    float* sM  = smem + 20864;   // 64 x 68

    int tid = threadIdx.x;
    for (int i = tid; i < 128 * 64; i += 256) sW1[i] = nW1[i];
    for (int i = tid; i < 64 * 64; i += 256) sW2[i] = nW2[i];
    if (tid < 64) { sb1[tid] = nb1[tid]; sb2[tid] = nb2[tid]; }

    int nbase = blockIdx.x * 64;

    // fused x update: 64 nodes * 3 coords = 192 elements
    if (tid < 192) {
        int node = nbase + tid / 3;
        if (node < NN) {
            int idx = node * 3 + tid % 3;
            float v = (g_x[idx] + g_dx[idx]) * node_mask[node];
            g_x[idx] = v;
            g_dx[idx] = 0.0f;
        }
    }

    for (int i = tid; i < 64 * 128; i += 256) {
        int nl = i >> 7, k = i & 127;
        int node = nbase + nl;
        float v = 0.0f;
        if (node < NN) {
            if (k < 64) v = g_h[node * 64 + k];
            else { v = g_agg[node * 64 + (k - 64)]; g_agg[node * 64 + (k - 64)] = 0.0f; }
        }
        sA[nl * 132 + k] = v;
    }
    __syncthreads();

    int ty = tid >> 4, tx = tid & 15;
    int r0 = ty * 4, c0 = tx * 4;

    float acc[4][4];
#pragma unroll
    for (int i = 0; i < 4; i++)
#pragma unroll
        for (int j = 0; j < 4; j++) acc[i][j] = 0.0f;
#pragma unroll 4
    for (int k = 0; k < 128; k++) {
        float4 wv = *(const float4*)(sW1 + k * 64 + c0);
        float w0 = wv.x, w1 = wv.y, w2 = wv.z, w3 = wv.w;
#pragma unroll
        for (int i = 0; i < 4; i++) {
            float a = sA[(r0 + i) * 132 + k];
            acc[i][0] = fmaf(a, w0, acc[i][0]);
            acc[i][1] = fmaf(a, w1, acc[i][1]);
            acc[i][2] = fmaf(a, w2, acc[i][2]);
            acc[i][3] = fmaf(a, w3, acc[i][3]);
        }
    }
#pragma unroll
    for (int i = 0; i < 4; i++)
#pragma unroll
        for (int j = 0; j < 4; j++)
            sM[(r0 + i) * 68 + c0 + j] = silu_f(acc[i][j] + sb1[c0 + j]);
    __syncthreads();

#pragma unroll
    for (int i = 0; i < 4; i++)
#pragma unroll
        for (int j = 0; j < 4; j++) acc[i][j] = 0.0f;
#pragma unroll 4
    for (int k = 0; k < 64; k++) {
        float4 wv = *(const float4*)(sW2 + k * 64 + c0);
        float w0 = wv.x, w1 = wv.y, w2 = wv.z, w3 = wv.w;
#pragma unroll
        for (int i = 0; i < 4; i++) {
            float a = sM[(r0 + i) * 68 + k];
            acc[i][0] = fmaf(a, w0, acc[i][0]);
            acc[i][1] = fmaf(a, w1, acc[i][1]);
            acc[i][2] = fmaf(a, w2, acc[i][2]);
            acc[i][3] = fmaf(a, w3, acc[i][3]);
        }
    }
#pragma unroll
    for (int i = 0; i < 4; i++) {
        int node = nbase + r0 + i;
        if (node < NN) {
            float msk = node_mask[node];
#pragma unroll
            for (int j = 0; j < 4; j++) {
                int idx = node * 64 + c0 + j;
                g_h[idx] = (g_h[idx] + acc[i][j] + sb2[c0 + j]) * msk;
            }
        }
    }
}

// ---------------------------------------------------------------- outputs
__global__ void k_out_h(const float* __restrict__ W, const float* __restrict__ b,
                        const float* __restrict__ node_mask, float* __restrict__ out) {
    __shared__ float sW[64 * 16];
    __shared__ float sb[16];
    int tid = threadIdx.x;
    for (int i = tid; i < 64 * 16; i += blockDim.x) sW[i] = W[i];
    if (tid < 16) sb[tid] = b[tid];
    __syncthreads();
    int gid = blockIdx.x * blockDim.x + tid;
    if (gid >= NN * 16) return;
    int n = gid >> 4, j = gid & 15;
    float acc = sb[j];
#pragma unroll
    for (int k = 0; k < 64; k++) acc += g_h[n * 64 + k] * sW[k * 16 + j];
    out[gid] = acc * node_mask[n];
}

__global__ void k_out_x(float* __restrict__ out) {
    int i = blockIdx.x * blockDim.x + threadIdx.x;
    if (i < NN * 3) out[i] = g_x[i];
}

__global__ void k_out_e(const float* __restrict__ W, const float* __restrict__ b,
                        const float* __restrict__ edge_mask, float* __restrict__ out) {
    __shared__ float sW[64 * 8];
    __shared__ float sb[8];
    int tid = threadIdx.x;
    for (int i = tid; i < 64 * 8; i += blockDim.x) sW[i] = W[i];
    if (tid < 8) sb[tid] = b[tid];
    __syncthreads();
    int gid = blockIdx.x * blockDim.x + tid;
    if (gid >= NE * 8) return;
    int e = gid >> 3, j = gid & 7;
    float acc = sb[j];
#pragma unroll
    for (int k = 0; k < 64; k++) acc += g_e[(size_t)e * 64 + k] * sW[k * 8 + j];
    out[gid] = acc * edge_mask[e];
}

// ---------------------------------------------------------------- launch
extern "C" void kernel_launch(void* const* d_in, const int* in_sizes, int n_in,
                              void* d_out, int out_size) {
    const float* h         = (const float*)d_in[0];
    const float* x         = (const float*)d_in[1];
    const float* edge_attr = (const float*)d_in[2];
    const float* node_mask = (const float*)d_in[3];
    const float* edge_mask = (const float*)d_in[4];
    const float* Wn_in  = (const float*)d_in[5];
    const float* bn_in  = (const float*)d_in[6];
    const float* Wn_out = (const float*)d_in[7];
    const float* bn_out = (const float*)d_in[8];
    const float* We_in  = (const float*)d_in[9];
    const float* be_in  = (const float*)d_in[10];
    const float* We_out = (const float*)d_in[11];
    const float* be_out = (const float*)d_in[12];
    const float* eW1 = (const float*)d_in[13];
    const float* eb1 = (const float*)d_in[14];
    const float* eW2 = (const float*)d_in[15];
    const float* eb2 = (const float*)d_in[16];
    const float* nW1 = (const float*)d_in[17];
    const float* nb1 = (const float*)d_in[18];
    const float* nW2 = (const float*)d_in[19];
    const float* nb2 = (const float*)d_in[20];
    const float* cW1 = (const float*)d_in[21];
    const float* cb1 = (const float*)d_in[22];
    const float* cW2 = (const float*)d_in[23];
    const int* edge_index = (const int*)d_in[24];
    float* out = (float*)d_out;

    cudaFuncSetAttribute(k_edge, cudaFuncAttributeMaxDynamicSharedMemorySize, EDGE_SMEM);
    cudaFuncSetAttribute(k_node, cudaFuncAttributeMaxDynamicSharedMemorySize, NODE_SMEM);

    k_node_embed<<<(NN * HD + 255) / 256, 256>>>(h, Wn_in, bn_in);
    k_edge_embed<<<(NE * HD + 255) / 256, 256>>>(edge_attr, We_in, be_in);
    k_xinit<<<(NN * 3 + 255) / 256, 256>>>(x);

    for (int l = 0; l < NLAYERS; l++) {
        k_edge<<<NE / 128, 1024, EDGE_SMEM>>>(
            eW1 + (size_t)l * EK * 64, eb1 + l * 64,
            eW2 + (size_t)l * 64 * 64, eb2 + l * 64,
            cW1 + (size_t)l * 64 * 64, cb1 + l * 64,
            cW2 + (size_t)l * 64,
            edge_index, edge_mask);
        k_node<<<(NN + 63) / 64, 256, NODE_SMEM>>>(
            nW1 + (size_t)l * 128 * 64, nb1 + l * 64,
            nW2 + (size_t)l * 64 * 64, nb2 + l * 64,
            node_mask);
    }

    k_out_h<<<(NN * 16 + 255) / 256, 256>>>(Wn_out, bn_out, node_mask, out);
    k_out_x<<<(NN * 3 + 255) / 256, 256>>>(out + NN * 16);
    k_out_e<<<(NE * 8 + 255) / 256, 256>>>(We_out, be_out, edge_mask, out + NN * 16 + NN * 3);
}

// round 11
// speedup vs baseline: 1.0988x; 1.0988x over previous
#include <cuda_runtime.h>
#include <math.h>

#define NN 50000
#define NE 800000
#define HD 64
#define NLAYERS 4
#define EK 193           // 2H + 1 + H (logical); padded to 196 in smem
#define EKP 196          // padded K, 16B-aligned stride, 196 mod 32 = 4
#define SMS 68           // activation stride: 16B-aligned, 68 mod 32 = 4

// ---- edge kernel smem layout (floats), 128 edges / 1024 threads ----
#define SW1_OFF   0                    // 196*64 = 12544 (rows 193..195 zero)
#define SW2_OFF   12544                // 64*64 = 4096
#define SWC1_OFF  16640                // 64*64 = 4096
#define SWC2_OFF  20736                // 64
#define SB1_OFF   20800                // 64
#define SB2_OFF   20864                // 64
#define SBC1_OFF  20928                // 64
#define SROW_OFF  20992                // 128 (int)
#define SCOL_OFF  21120                // 128 (int)
#define SRAD_OFF  21248                // 128
#define SEM_OFF   21376                // 128
#define SCD_OFF   21504                // 128*3 = 384
#define SA_OFF    21888                // 128*196 = 25088 (overlaid below)
#define SM1_OFF   21888                // overlay: 128*68 = 8704
#define SM2_OFF   (21888 + 8704)       // overlay: 128*68 = 8704
#define SS_OFF    (21888 + 17408)      // overlay: 128*16 = 2048
#define EDGE_SMEM_FLOATS (SA_OFF + 128 * EKP)   // 46976
#define EDGE_SMEM (EDGE_SMEM_FLOATS * 4)        // 187,904 B

#define NODE_SMEM (25216 * 4)

// persistent scratch (no runtime allocation allowed)
__device__ float g_h[NN * HD];
__device__ float g_e[NE * HD];
__device__ float g_x[NN * 3];
__device__ float g_dx[NN * 3];    // zero-initialized; restored to zero after use
__device__ float g_agg[NN * HD];  // zero-initialized; restored to zero after use

__device__ __forceinline__ float silu_f(float v) {
    return v / (1.0f + __expf(-v));
}

__device__ __forceinline__ void fma_row(float a, float4 w, float* accr) {
    accr[0] = fmaf(a, w.x, accr[0]);
    accr[1] = fmaf(a, w.y, accr[1]);
    accr[2] = fmaf(a, w.z, accr[2]);
    accr[3] = fmaf(a, w.w, accr[3]);
}

// ---------------------------------------------------------------- embeddings
__global__ void k_node_embed(const float* __restrict__ h,
                             const float* __restrict__ W,
                             const float* __restrict__ b) {
    __shared__ float sW[16 * 64];
    __shared__ float sb[64];
    int tid = threadIdx.x;
    for (int i = tid; i < 16 * 64; i += blockDim.x) sW[i] = W[i];
    if (tid < 64) sb[tid] = b[tid];
    __syncthreads();
    int gid = blockIdx.x * blockDim.x + tid;
    if (gid >= NN * HD) return;
    int n = gid >> 6, j = gid & 63;
    float acc = sb[j];
#pragma unroll
    for (int k = 0; k < 16; k++) acc += h[n * 16 + k] * sW[k * 64 + j];
    g_h[gid] = acc;
}

__global__ void k_edge_embed(const float* __restrict__ ea,
                             const float* __restrict__ W,
                             const float* __restrict__ b) {
    __shared__ float sW[8 * 64];
    __shared__ float sb[64];
    int tid = threadIdx.x;
    for (int i = tid; i < 8 * 64; i += blockDim.x) sW[i] = W[i];
    if (tid < 64) sb[tid] = b[tid];
    __syncthreads();
    int gid = blockIdx.x * blockDim.x + tid;
    if (gid >= NE * HD) return;
    int e = gid >> 6, j = gid & 63;
    float acc = sb[j];
#pragma unroll
    for (int k = 0; k < 8; k++) acc += ea[e * 8 + k] * sW[k * 64 + j];
    g_e[gid] = acc;
}

__global__ void k_xinit(const float* __restrict__ x) {
    int i = blockIdx.x * blockDim.x + threadIdx.x;
    if (i < NN * 3) g_x[i] = x[i];
}

// ---------------------------------------------------------------- edge layer
// 1024 threads = 64 row-groups x 16 col-groups; thread owns 2 edges x 4 outputs.
// Per 4-k tile: 2x LDS.128 A (2 distinct lines/warp -> broadcast)
//             + 4x LDS.128 W (16 distinct lines/warp -> 2 phases) per 32 FFMA.
__global__ void __launch_bounds__(1024, 1)
k_edge(const float* __restrict__ eW1, const float* __restrict__ eb1,
       const float* __restrict__ eW2, const float* __restrict__ eb2,
       const float* __restrict__ cW1, const float* __restrict__ cb1,
       const float* __restrict__ cW2,
       const int* __restrict__ edge_index,
       const float* __restrict__ edge_mask) {
    extern __shared__ float smem[];
    float* sW1  = smem + SW1_OFF;
    float* sW2  = smem + SW2_OFF;
    float* sWc1 = smem + SWC1_OFF;
    float* sWc2 = smem + SWC2_OFF;
    float* sb1  = smem + SB1_OFF;
    float* sb2  = smem + SB2_OFF;
    float* sbc1 = smem + SBC1_OFF;
    int*   sRow = (int*)(smem + SROW_OFF);
    int*   sCol = (int*)(smem + SCOL_OFF);
    float* sRad = smem + SRAD_OFF;
    float* sEM  = smem + SEM_OFF;
    float* sCD  = smem + SCD_OFF;
    float* sA   = smem + SA_OFF;     // 128 x 196
    float* sM1  = smem + SM1_OFF;    // overlay
    float* sM2  = smem + SM2_OFF;    // overlay
    float* sS   = smem + SS_OFF;     // overlay

    int tid = threadIdx.x;
    // stage weights; W1 rows 193..195 zeroed
    for (int i = tid; i < EKP * 64; i += 1024)
        sW1[i] = (i < EK * 64) ? eW1[i] : 0.0f;
    for (int i = tid; i < 64 * 64; i += 1024) { sW2[i] = eW2[i]; sWc1[i] = cW1[i]; }
    if (tid < 64) { sWc2[tid] = cW2[tid]; sb1[tid] = eb1[tid]; sb2[tid] = eb2[tid]; sbc1[tid] = cb1[tid]; }

    int ebase = blockIdx.x * 128;
    if (tid < 128) {
        int e = ebase + tid;
        int r = edge_index[e];
        int c = edge_index[NE + e];
        sRow[tid] = r; sCol[tid] = c;
        float dx = g_x[r * 3 + 0] - g_x[c * 3 + 0];
        float dy = g_x[r * 3 + 1] - g_x[c * 3 + 1];
        float dz = g_x[r * 3 + 2] - g_x[c * 3 + 2];
        float rad = dx * dx + dy * dy + dz * dz;
        sRad[tid] = rad;
        float inv = 1.0f / (sqrtf(rad) + 1.0f);
        sCD[tid * 3 + 0] = dx * inv;
        sCD[tid * 3 + 1] = dy * inv;
        sCD[tid * 3 + 2] = dz * inv;
        sEM[tid] = edge_mask[e];
    }
    __syncthreads();

    // build A = [h[row] | h[col] | radial | e | 0 0 0]  (128 x 196)
    for (int i = tid; i < 128 * EKP; i += 1024) {
        int el = i / EKP;
        int k  = i - el * EKP;
        float v;
        if (k < 64)        v = g_h[sRow[el] * 64 + k];
        else if (k < 128)  v = g_h[sCol[el] * 64 + (k - 64)];
        else if (k == 128) v = sRad[el];
        else if (k < EK)   v = g_e[(size_t)(ebase + el) * 64 + (k - 129)];
        else               v = 0.0f;
        sA[i] = v;
    }
    __syncthreads();

    int tx = tid & 15, ty = tid >> 4;   // tx: col-group (16), ty: row-group (64)
    int r0 = ty * 2, c0 = tx * 4;

    float acc[2][4];
#pragma unroll
    for (int i = 0; i < 2; i++)
#pragma unroll
        for (int j = 0; j < 4; j++) acc[i][j] = 0.0f;

    // GEMM1: [128x196] @ [196x64], 49 k-tiles of 4
    {
        const float* ap = sA + r0 * EKP;
        const float* wp = sW1 + c0;
#pragma unroll 7
        for (int kt = 0; kt < 49; kt++) {
            int k0 = kt * 4;
            float4 a0 = *(const float4*)(ap + k0);
            float4 a1 = *(const float4*)(ap + EKP + k0);
            float4 w0 = *(const float4*)(wp + (k0 + 0) * 64);
            float4 w1 = *(const float4*)(wp + (k0 + 1) * 64);
            float4 w2 = *(const float4*)(wp + (k0 + 2) * 64);
            float4 w3 = *(const float4*)(wp + (k0 + 3) * 64);
            fma_row(a0.x, w0, acc[0]); fma_row(a1.x, w0, acc[1]);
            fma_row(a0.y, w1, acc[0]); fma_row(a1.y, w1, acc[1]);
            fma_row(a0.z, w2, acc[0]); fma_row(a1.z, w2, acc[1]);
            fma_row(a0.w, w3, acc[0]); fma_row(a1.w, w3, acc[1]);
        }
    }
    __syncthreads();   // all sA reads complete; overlay region free

    // m1 = silu(acc + b1) -> sM1 (stride 68, float4 stores)
#pragma unroll
    for (int i = 0; i < 2; i++) {
        float4 v;
        v.x = silu_f(acc[i][0] + sb1[c0 + 0]);
        v.y = silu_f(acc[i][1] + sb1[c0 + 1]);
        v.z = silu_f(acc[i][2] + sb1[c0 + 2]);
        v.w = silu_f(acc[i][3] + sb1[c0 + 3]);
        *(float4*)(sM1 + (r0 + i) * SMS + c0) = v;
    }
    __syncthreads();

    // GEMM2: K = 64 over sM1, 16 k-tiles
#pragma unroll
    for (int i = 0; i < 2; i++)
#pragma unroll
        for (int j = 0; j < 4; j++) acc[i][j] = 0.0f;
    {
        const float* ap = sM1 + r0 * SMS;
        const float* wp = sW2 + c0;
#pragma unroll 4
        for (int kt = 0; kt < 16; kt++) {
            int k0 = kt * 4;
            float4 a0 = *(const float4*)(ap + k0);
            float4 a1 = *(const float4*)(ap + SMS + k0);
            float4 w0 = *(const float4*)(wp + (k0 + 0) * 64);
            float4 w1 = *(const float4*)(wp + (k0 + 1) * 64);
            float4 w2 = *(const float4*)(wp + (k0 + 2) * 64);
            float4 w3 = *(const float4*)(wp + (k0 + 3) * 64);
            fma_row(a0.x, w0, acc[0]); fma_row(a1.x, w0, acc[1]);
            fma_row(a0.y, w1, acc[0]); fma_row(a1.y, w1, acc[1]);
            fma_row(a0.z, w2, acc[0]); fma_row(a1.z, w2, acc[1]);
            fma_row(a0.w, w3, acc[0]); fma_row(a1.w, w3, acc[1]);
        }
    }

    // m = silu(acc + b2) * edge_mask -> g_e, g_agg (atomic), sM2
#pragma unroll
    for (int i = 0; i < 2; i++) {
        float em = sEM[r0 + i];
        float4 v;
        v.x = silu_f(acc[i][0] + sb2[c0 + 0]) * em;
        v.y = silu_f(acc[i][1] + sb2[c0 + 1]) * em;
        v.z = silu_f(acc[i][2] + sb2[c0 + 2]) * em;
        v.w = silu_f(acc[i][3] + sb2[c0 + 3]) * em;
        *(float4*)(g_e + (size_t)(ebase + r0 + i) * 64 + c0) = v;
        *(float4*)(sM2 + (r0 + i) * SMS + c0) = v;
        float* ga = g_agg + (size_t)sRow[r0 + i] * 64 + c0;
        atomicAdd(ga + 0, v.x);
        atomicAdd(ga + 1, v.y);
        atomicAdd(ga + 2, v.z);
        atomicAdd(ga + 3, v.w);
    }
    __syncthreads();

    // GEMM3 (coord head): c1 = silu(m@cW1+cb1); partial = sum_j c1[j]*cW2[j]
#pragma unroll
    for (int i = 0; i < 2; i++)
#pragma unroll
        for (int j = 0; j < 4; j++) acc[i][j] = 0.0f;
    {
        const float* ap = sM2 + r0 * SMS;
        const float* wp = sWc1 + c0;
#pragma unroll 4
        for (int kt = 0; kt < 16; kt++) {
            int k0 = kt * 4;
            float4 a0 = *(const float4*)(ap + k0);
            float4 a1 = *(const float4*)(ap + SMS + k0);
            float4 w0 = *(const float4*)(wp + (k0 + 0) * 64);
            float4 w1 = *(const float4*)(wp + (k0 + 1) * 64);
            float4 w2 = *(const float4*)(wp + (k0 + 2) * 64);
            float4 w3 = *(const float4*)(wp + (k0 + 3) * 64);
            fma_row(a0.x, w0, acc[0]); fma_row(a1.x, w0, acc[1]);
            fma_row(a0.y, w1, acc[0]); fma_row(a1.y, w1, acc[1]);
            fma_row(a0.z, w2, acc[0]); fma_row(a1.z, w2, acc[1]);
            fma_row(a0.w, w3, acc[0]); fma_row(a1.w, w3, acc[1]);
        }
    }
#pragma unroll
    for (int i = 0; i < 2; i++) {
        float p = 0.0f;
#pragma unroll
        for (int j = 0; j < 4; j++)
            p += silu_f(acc[i][j] + sbc1[c0 + j]) * sWc2[c0 + j];
        sS[(r0 + i) * 16 + tx] = p;
    }
    __syncthreads();
    if (tid < 128) {
        float s = 0.0f;
#pragma unroll
        for (int u = 0; u < 16; u++) s += sS[tid * 16 + u];
        int r = sRow[tid];
        atomicAdd(&g_dx[r * 3 + 0], sCD[tid * 3 + 0] * s);
        atomicAdd(&g_dx[r * 3 + 1], sCD[tid * 3 + 1] * s);
        atomicAdd(&g_dx[r * 3 + 2], sCD[tid * 3 + 2] * s);
    }
}

// ---------------------------------------------------------------- node layer
// Also performs the x update for its 64 nodes (edge scatters complete at
// kernel boundary): x = (x + dx) * mask; dx = 0.
__global__ void __launch_bounds__(256, 1)
k_node(const float* __restrict__ nW1, const float* __restrict__ nb1,
       const float* __restrict__ nW2, const float* __restrict__ nb2,
       const float* __restrict__ node_mask) {
    extern __shared__ float smem[];
    float* sW1 = smem;           // 128*64
    float* sW2 = smem + 8192;    // 64*64
    float* sb1 = smem + 12288;
    float* sb2 = smem + 12352;
    float* sA  = smem + 12416;   // 64 x 132
    float* sM  = smem + 20864;   // 64 x 68

    int tid = threadIdx.x;
    for (int i = tid; i < 128 * 64; i += 256) sW1[i] = nW1[i];
    for (int i = tid; i < 64 * 64; i += 256) sW2[i] = nW2[i];
    if (tid < 64) { sb1[tid] = nb1[tid]; sb2[tid] = nb2[tid]; }

    int nbase = blockIdx.x * 64;

    // fused x update: 64 nodes * 3 coords = 192 elements
    if (tid < 192) {
        int node = nbase + tid / 3;
        if (node < NN) {
            int idx = node * 3 + tid % 3;
            float v = (g_x[idx] + g_dx[idx]) * node_mask[node];
            g_x[idx] = v;
            g_dx[idx] = 0.0f;
        }
    }

    for (int i = tid; i < 64 * 128; i += 256) {
        int nl = i >> 7, k = i & 127;
        int node = nbase + nl;
        float v = 0.0f;
        if (node < NN) {
            if (k < 64) v = g_h[node * 64 + k];
            else { v = g_agg[node * 64 + (k - 64)]; g_agg[node * 64 + (k - 64)] = 0.0f; }
        }
        sA[nl * 132 + k] = v;
    }
    __syncthreads();

    int ty = tid >> 4, tx = tid & 15;
    int r0 = ty * 4, c0 = tx * 4;

    float acc[4][4];
#pragma unroll
    for (int i = 0; i < 4; i++)
#pragma unroll
        for (int j = 0; j < 4; j++) acc[i][j] = 0.0f;
#pragma unroll 4
    for (int k = 0; k < 128; k++) {
        float4 wv = *(const float4*)(sW1 + k * 64 + c0);
        float w0 = wv.x, w1 = wv.y, w2 = wv.z, w3 = wv.w;
#pragma unroll
        for (int i = 0; i < 4; i++) {
            float a = sA[(r0 + i) * 132 + k];
            acc[i][0] = fmaf(a, w0, acc[i][0]);
            acc[i][1] = fmaf(a, w1, acc[i][1]);
            acc[i][2] = fmaf(a, w2, acc[i][2]);
            acc[i][3] = fmaf(a, w3, acc[i][3]);
        }
    }
#pragma unroll
    for (int i = 0; i < 4; i++)
#pragma unroll
        for (int j = 0; j < 4; j++)
            sM[(r0 + i) * 68 + c0 + j] = silu_f(acc[i][j] + sb1[c0 + j]);
    __syncthreads();

#pragma unroll
    for (int i = 0; i < 4; i++)
#pragma unroll
        for (int j = 0; j < 4; j++) acc[i][j] = 0.0f;
#pragma unroll 4
    for (int k = 0; k < 64; k++) {
        float4 wv = *(const float4*)(sW2 + k * 64 + c0);
        float w0 = wv.x, w1 = wv.y, w2 = wv.z, w3 = wv.w;
#pragma unroll
        for (int i = 0; i < 4; i++) {
            float a = sM[(r0 + i) * 68 + k];
            acc[i][0] = fmaf(a, w0, acc[i][0]);
            acc[i][1] = fmaf(a, w1, acc[i][1]);
            acc[i][2] = fmaf(a, w2, acc[i][2]);
            acc[i][3] = fmaf(a, w3, acc[i][3]);
        }
    }
#pragma unroll
    for (int i = 0; i < 4; i++) {
        int node = nbase + r0 + i;
        if (node < NN) {
            float msk = node_mask[node];
#pragma unroll
            for (int j = 0; j < 4; j++) {
                int idx = node * 64 + c0 + j;
                g_h[idx] = (g_h[idx] + acc[i][j] + sb2[c0 + j]) * msk;
            }
        }
    }
}

// ---------------------------------------------------------------- outputs
__global__ void k_out_h(const float* __restrict__ W, const float* __restrict__ b,
                        const float* __restrict__ node_mask, float* __restrict__ out) {
    __shared__ float sW[64 * 16];
    __shared__ float sb[16];
    int tid = threadIdx.x;
    for (int i = tid; i < 64 * 16; i += blockDim.x) sW[i] = W[i];
    if (tid < 16) sb[tid] = b[tid];
    __syncthreads();
    int gid = blockIdx.x * blockDim.x + tid;
    if (gid >= NN * 16) return;
    int n = gid >> 4, j = gid & 15;
    float acc = sb[j];
#pragma unroll
    for (int k = 0; k < 64; k++) acc += g_h[n * 64 + k] * sW[k * 16 + j];
    out[gid] = acc * node_mask[n];
}

__global__ void k_out_x(float* __restrict__ out) {
    int i = blockIdx.x * blockDim.x + threadIdx.x;
    if (i < NN * 3) out[i] = g_x[i];
}

__global__ void k_out_e(const float* __restrict__ W, const float* __restrict__ b,
                        const float* __restrict__ edge_mask, float* __restrict__ out) {
    __shared__ float sW[64 * 8];
    __shared__ float sb[8];
    int tid = threadIdx.x;
    for (int i = tid; i < 64 * 8; i += blockDim.x) sW[i] = W[i];
    if (tid < 8) sb[tid] = b[tid];
    __syncthreads();
    int gid = blockIdx.x * blockDim.x + tid;
    if (gid >= NE * 8) return;
    int e = gid >> 3, j = gid & 7;
    float acc = sb[j];
#pragma unroll
    for (int k = 0; k < 64; k++) acc += g_e[(size_t)e * 64 + k] * sW[k * 8 + j];
    out[gid] = acc * edge_mask[e];
}

// ---------------------------------------------------------------- launch
extern "C" void kernel_launch(void* const* d_in, const int* in_sizes, int n_in,
                              void* d_out, int out_size) {
    const float* h         = (const float*)d_in[0];
    const float* x         = (const float*)d_in[1];
    const float* edge_attr = (const float*)d_in[2];
    const float* node_mask = (const float*)d_in[3];
    const float* edge_mask = (const float*)d_in[4];
    const float* Wn_in  = (const float*)d_in[5];
    const float* bn_in  = (const float*)d_in[6];
    const float* Wn_out = (const float*)d_in[7];
    const float* bn_out = (const float*)d_in[8];
    const float* We_in  = (const float*)d_in[9];
    const float* be_in  = (const float*)d_in[10];
    const float* We_out = (const float*)d_in[11];
    const float* be_out = (const float*)d_in[12];
    const float* eW1 = (const float*)d_in[13];
    const float* eb1 = (const float*)d_in[14];
    const float* eW2 = (const float*)d_in[15];
    const float* eb2 = (const float*)d_in[16];
    const float* nW1 = (const float*)d_in[17];
    const float* nb1 = (const float*)d_in[18];
    const float* nW2 = (const float*)d_in[19];
    const float* nb2 = (const float*)d_in[20];
    const float* cW1 = (const float*)d_in[21];
    const float* cb1 = (const float*)d_in[22];
    const float* cW2 = (const float*)d_in[23];
    const int* edge_index = (const int*)d_in[24];
    float* out = (float*)d_out;

    cudaFuncSetAttribute(k_edge, cudaFuncAttributeMaxDynamicSharedMemorySize, EDGE_SMEM);
    cudaFuncSetAttribute(k_node, cudaFuncAttributeMaxDynamicSharedMemorySize, NODE_SMEM);

    k_node_embed<<<(NN * HD + 255) / 256, 256>>>(h, Wn_in, bn_in);
    k_edge_embed<<<(NE * HD + 255) / 256, 256>>>(edge_attr, We_in, be_in);
    k_xinit<<<(NN * 3 + 255) / 256, 256>>>(x);

    for (int l = 0; l < NLAYERS; l++) {
        k_edge<<<NE / 128, 1024, EDGE_SMEM>>>(
            eW1 + (size_t)l * EK * 64, eb1 + l * 64,
            eW2 + (size_t)l * 64 * 64, eb2 + l * 64,
            cW1 + (size_t)l * 64 * 64, cb1 + l * 64,
            cW2 + (size_t)l * 64,
            edge_index, edge_mask);
        k_node<<<(NN + 63) / 64, 256, NODE_SMEM>>>(
            nW1 + (size_t)l * 128 * 64, nb1 + l * 64,
            nW2 + (size_t)l * 64 * 64, nb2 + l * 64,
            node_mask);
    }

    k_out_h<<<(NN * 16 + 255) / 256, 256>>>(Wn_out, bn_out, node_mask, out);
    k_out_x<<<(NN * 3 + 255) / 256, 256>>>(out + NN * 16);
    k_out_e<<<(NE * 8 + 255) / 256, 256>>>(We_out, be_out, edge_mask, out + NN * 16 + NN * 3);
}